// round 2
// baseline (speedup 1.0000x reference)
#include <cuda_runtime.h>
#include <math.h>

#define BB    128
#define TT    2048
#define KD    128
#define VD    128
#define HD    300
#define ED    400
#define NV    33
#define G4    1200
#define SOS   5
#define STEPS 500
#define NBLK  128
#define NTHR  512

// ---------------- persistent device state ----------------
__device__ float g_hA[BB * HD];
__device__ float g_hB[BB * HD];
__device__ float g_c[BB * HD];
__device__ float g_ctx[BB * VD];
__device__ float g_ge[NV * G4];   // emb @ W_ih[:, :400]^T + b_ih + b_hh
__device__ int   g_char[BB];
__device__ unsigned g_count;
__device__ volatile unsigned g_sense;

// ---------------- grid barrier (monotonic epoch) ----------------
__device__ __forceinline__ void gbar(unsigned e) {
    __syncthreads();
    if (threadIdx.x == 0) {
        __threadfence();
        unsigned prev = atomicAdd(&g_count, 1u);
        if (prev == e * NBLK - 1u) {
            g_sense = e;                       // release
        } else {
            while (g_sense < e) { }            // spin on L2
        }
        __threadfence();
    }
    __syncthreads();
}

// ---------------- init: precompute + state/barrier reset ----------------
__global__ void init_kernel(const float* __restrict__ emb,
                            const float* __restrict__ W_ih,
                            const float* __restrict__ b_ih,
                            const float* __restrict__ b_hh,
                            const float* __restrict__ h0,
                            const float* __restrict__ c0) {
    int blk = blockIdx.x, tid = threadIdx.x;
    if (blk < NV) {
        __shared__ float e_s[ED];
        for (int i = tid; i < ED; i += blockDim.x) e_s[i] = emb[blk * ED + i];
        __syncthreads();
        int wid = tid >> 5, lane = tid & 31;
        for (int j = wid; j < G4; j += 8) {
            float acc = 0.f;
            const float* wr = W_ih + (size_t)j * 528;
            for (int k = lane; k < ED; k += 32) acc += e_s[k] * wr[k];
            #pragma unroll
            for (int o = 16; o; o >>= 1) acc += __shfl_xor_sync(0xffffffffu, acc, o);
            if (lane == 0) g_ge[blk * G4 + j] = acc + b_ih[j] + b_hh[j];
        }
    } else {
        for (int i = tid; i < BB * HD; i += blockDim.x) {
            g_hA[i] = h0[i % HD];
            g_c[i]  = c0[i % HD];
        }
        for (int i = tid; i < BB; i += blockDim.x) g_char[i] = SOS;
        if (tid == 0) { g_count = 0u; g_sense = 0u; }
    }
}

// ---------------- attend phase (+ fused logits/argmax prologue) ----------------
__device__ void attend_phase(int b, const float* __restrict__ hbuf, int s,
                             const float* __restrict__ keys,
                             const float* __restrict__ values,
                             const float* __restrict__ W_phi,
                             const float* __restrict__ b_phi,
                             const float* __restrict__ W_proj,
                             const float* __restrict__ b_proj,
                             float* __restrict__ out, int write_preds,
                             float* sm) {
    int tid = threadIdx.x, wid = tid >> 5, lane = tid & 31;
    float* w_s   = sm;          // 2048
    float* h_s   = sm + 2048;   // 304
    float* q_s   = sm + 2352;   // 128 (16B aligned)
    float* ctx_s = sm + 2480;   // 128
    float* cpart = sm + 2608;   // 1024
    float* lg_s  = sm + 3632;   // 36
    float* red   = sm + 3668;   // 16
    float* bc    = sm + 3684;   // 2

    for (int i = tid; i < HD; i += NTHR) h_s[i] = __ldcg(&hbuf[b * HD + i]);
    for (int i = tid; i < VD; i += NTHR) ctx_s[i] = __ldcg(&g_ctx[b * VD + i]);
    __syncthreads();

    if (s >= 0) {
        // logits: h_new + previous context
        for (int v = wid; v < NV; v += 16) {
            float acc = 0.f;
            const float* wr = W_proj + (size_t)v * 428;
            for (int k = lane; k < 428; k += 32) {
                float x = (k < HD) ? h_s[k] : ctx_s[k - HD];
                acc += x * wr[k];
            }
            #pragma unroll
            for (int o = 16; o; o >>= 1) acc += __shfl_xor_sync(0xffffffffu, acc, o);
            if (lane == 0) lg_s[v] = acc + b_proj[v];
        }
        __syncthreads();
        if (tid < NV) out[(size_t)s * (BB * NV) + b * NV + tid] = lg_s[tid];
        if (tid == 0) {
            int am = 0; float mv = lg_s[0];
            for (int v = 1; v < NV; ++v) if (lg_s[v] > mv) { mv = lg_s[v]; am = v; }
            __stcg(&g_char[b], am);
            if (write_preds)
                out[(size_t)STEPS * BB * NV + (size_t)s * BB + b] = (float)am;
        }
    }

    // query = h @ W_phi^T + b_phi
    for (int q = wid; q < KD; q += 16) {
        float acc = 0.f;
        const float* wr = W_phi + (size_t)q * HD;
        for (int k = lane; k < HD; k += 32) acc += h_s[k] * wr[k];
        #pragma unroll
        for (int o = 16; o; o >>= 1) acc += __shfl_xor_sync(0xffffffffu, acc, o);
        if (lane == 0) q_s[q] = acc + b_phi[q];
    }
    __syncthreads();

    // energies: 16 warps x 8 t per iter, batched 512B coalesced loads
    float4 qv = ((const float4*)q_s)[lane];
    const float4* kbase = (const float4*)keys + (size_t)b * 32 + lane;
    for (int t0 = wid * 8; t0 < TT; t0 += 128) {
        float4 kv[8];
        #pragma unroll
        for (int i = 0; i < 8; i++)
            kv[i] = __ldg(kbase + (size_t)(t0 + i) * (BB * 32));
        #pragma unroll
        for (int i = 0; i < 8; i++) {
            float e = kv[i].x * qv.x + kv[i].y * qv.y + kv[i].z * qv.z + kv[i].w * qv.w;
            #pragma unroll
            for (int o = 16; o; o >>= 1) e += __shfl_xor_sync(0xffffffffu, e, o);
            if (lane == 0) w_s[t0 + i] = e;
        }
    }
    __syncthreads();

    // softmax max
    float m = -1e30f;
    for (int i = tid; i < TT; i += NTHR) m = fmaxf(m, w_s[i]);
    #pragma unroll
    for (int o = 16; o; o >>= 1) m = fmaxf(m, __shfl_xor_sync(0xffffffffu, m, o));
    if (lane == 0) red[wid] = m;
    __syncthreads();
    if (wid == 0) {
        float v = (lane < 16) ? red[lane] : -1e30f;
        #pragma unroll
        for (int o = 8; o; o >>= 1) v = fmaxf(v, __shfl_xor_sync(0xffffffffu, v, o));
        if (lane == 0) bc[0] = v;
    }
    __syncthreads();
    m = bc[0];

    // exp + sum
    float lsum = 0.f;
    for (int i = tid; i < TT; i += NTHR) {
        float e = expf(w_s[i] - m);
        w_s[i] = e;
        lsum += e;
    }
    #pragma unroll
    for (int o = 16; o; o >>= 1) lsum += __shfl_xor_sync(0xffffffffu, lsum, o);
    if (lane == 0) red[wid] = lsum;
    __syncthreads();
    if (wid == 0) {
        float v = (lane < 16) ? red[lane] : 0.f;
        #pragma unroll
        for (int o = 8; o; o >>= 1) v += __shfl_xor_sync(0xffffffffu, v, o);
        if (lane == 0) bc[1] = v;
    }
    __syncthreads();
    float inv = 1.f / bc[1];

    // context: 8 t-slices x 64 float2 lanes, 8-deep unroll
    {
        int v2 = tid & 63, qt = tid >> 6;
        const float2* vp = (const float2*)(values + (size_t)b * VD) + v2;
        float2 a = make_float2(0.f, 0.f);
        int tb = qt * 256;
        for (int t = tb; t < tb + 256; t += 8) {
            #pragma unroll
            for (int i = 0; i < 8; i++) {
                float2 vv = __ldg(vp + (size_t)(t + i) * (BB * VD / 2));
                a.x += w_s[t + i] * vv.x;
                a.y += w_s[t + i] * vv.y;
            }
        }
        cpart[qt * 128 + v2 * 2]     = a.x;
        cpart[qt * 128 + v2 * 2 + 1] = a.y;
    }
    __syncthreads();
    if (tid < 128) {
        float acc = 0.f;
        #pragma unroll
        for (int qt = 0; qt < 8; qt++) acc += cpart[qt * 128 + tid];
        __stcg(&g_ctx[b * VD + tid], acc * inv);
    }
    __syncthreads();
}

// ---------------- LSTM phase ----------------
__device__ void lstm_phase(int parity,
                           const float* __restrict__ W_ih,
                           const float* __restrict__ W_hh,
                           float* sm) {
    int cta = blockIdx.x;
    if (cta >= 120) return;
    int tid = threadIdx.x;
    int bt = cta / 15;          // 0..7  : 16 batches each
    int nt = cta % 15;          // 0..14 : 20 hidden units each
    const float* h_in  = parity ? g_hB : g_hA;
    float*       h_out = parity ? g_hA : g_hB;

    float* xx = sm;             // [16][432]
    // load x = [ctx(128), h(300)] for 16 batches
    for (int idx = tid; idx < 16 * 428; idx += NTHR) {
        int bl = idx / 428, k = idx - bl * 428;
        int bg = bt * 16 + bl;
        float v = (k < 128) ? __ldcg(&g_ctx[bg * 128 + k])
                            : __ldcg(&h_in[bg * 300 + (k - 128)]);
        xx[bl * 432 + k] = v;
    }
    __syncthreads();

    float acc[4][4];
    int ks = 0, rem = 0;
    if (tid < 320) {
        ks = tid / 80; rem = tid % 80;
        int rg = rem / 4, bg = rem % 4;
        int gq = (rg * 4) / 20, rl = (rg * 4) % 20;
        int row0 = gq * 300 + nt * 20 + rl;
        #pragma unroll
        for (int r = 0; r < 4; r++)
            #pragma unroll
            for (int bi = 0; bi < 4; bi++) acc[r][bi] = 0.f;

        int k4s = ks * 27, k4e = (ks == 3) ? 107 : (k4s + 27);
        const float4* xb[4];
        #pragma unroll
        for (int bi = 0; bi < 4; bi++)
            xb[bi] = (const float4*)(xx + (size_t)(bg * 4 + bi) * 432);

        // region 1: context cols (k4 in [k4s, min(k4e,32)))
        int e1 = k4e < 32 ? k4e : 32;
        for (int k4 = k4s; k4 < e1; k4++) {
            float4 w[4];
            #pragma unroll
            for (int r = 0; r < 4; r++)
                w[r] = __ldg((const float4*)(W_ih + (size_t)(row0 + r) * 528 + 400) + k4);
            #pragma unroll
            for (int bi = 0; bi < 4; bi++) {
                float4 x = xb[bi][k4];
                #pragma unroll
                for (int r = 0; r < 4; r++)
                    acc[r][bi] += w[r].x * x.x + w[r].y * x.y + w[r].z * x.z + w[r].w * x.w;
            }
        }
        // region 2: hidden cols (k4 in [max(k4s,32), k4e))
        int s2 = k4s > 32 ? k4s : 32;
        for (int k4 = s2; k4 < k4e; k4++) {
            float4 w[4];
            #pragma unroll
            for (int r = 0; r < 4; r++)
                w[r] = __ldg((const float4*)(W_hh + (size_t)(row0 + r) * 300) + (k4 - 32));
            #pragma unroll
            for (int bi = 0; bi < 4; bi++) {
                float4 x = xb[bi][k4];
                #pragma unroll
                for (int r = 0; r < 4; r++)
                    acc[r][bi] += w[r].x * x.x + w[r].y * x.y + w[r].z * x.z + w[r].w * x.w;
            }
        }
    }
    __syncthreads();            // xx reads done; reuse as partial buffer

    float* part = sm;           // 5120 floats
    float* gs   = sm + 5120;    // 1280 floats
    if (tid < 320) {
        #pragma unroll
        for (int r = 0; r < 4; r++)
            #pragma unroll
            for (int bi = 0; bi < 4; bi++)
                part[(rem * 16 + r * 4 + bi) * 4 + ks] = acc[r][bi];
    }
    __syncthreads();

    for (int o = tid; o < 1280; o += NTHR) {
        float sum = part[o * 4] + part[o * 4 + 1] + part[o * 4 + 2] + part[o * 4 + 3];
        int rm = o >> 4, ri = (o >> 2) & 3, bi = o & 3;
        int rg = rm >> 2, bg = rm & 3;
        int r = rg * 4 + ri;
        int bl = bg * 4 + bi;
        int gq = r / 20, nl = r % 20;
        int row = gq * 300 + nt * 20 + nl;
        int ch = __ldcg(&g_char[bt * 16 + bl]);
        sum += g_ge[ch * G4 + row];
        gs[(bl * 20 + nl) * 4 + gq] = sum;
    }
    __syncthreads();

    if (tid < 320) {
        int bl = tid / 20, nl = tid % 20;
        float4 gv = *(const float4*)(gs + (bl * 20 + nl) * 4);
        int bg = bt * 16 + bl, ng = nt * 20 + nl;
        float c_old = g_c[bg * 300 + ng];
        float ig = 1.f / (1.f + expf(-gv.x));
        float fg = 1.f / (1.f + expf(-gv.y));
        float gg = tanhf(gv.z);
        float og = 1.f / (1.f + expf(-gv.w));
        float cn = fg * c_old + ig * gg;
        float hn = og * tanhf(cn);
        g_c[bg * 300 + ng] = cn;
        __stcg(&h_out[bg * 300 + ng], hn);
    }
    __syncthreads();
}

// ---------------- persistent kernel: 1 launch, whole decode ----------------
__global__ void __launch_bounds__(NTHR, 1)
decoder_persistent(const float* __restrict__ keys,
                   const float* __restrict__ values,
                   const float* __restrict__ W_phi,
                   const float* __restrict__ b_phi,
                   const float* __restrict__ W_ih,
                   const float* __restrict__ W_hh,
                   const float* __restrict__ W_proj,
                   const float* __restrict__ b_proj,
                   float* __restrict__ out, int write_preds) {
    __shared__ float sm[7168];
    int cta = blockIdx.x;
    unsigned epoch = 0;

    // initial context = attend(h0), no logits
    attend_phase(cta, g_hA, -1, keys, values, W_phi, b_phi, W_proj, b_proj,
                 out, 0, sm);
    gbar(++epoch);

    for (int s = 0; s < STEPS; ++s) {
        lstm_phase(s & 1, W_ih, W_hh, sm);
        gbar(++epoch);
        attend_phase(cta, (s & 1) ? g_hA : g_hB, s, keys, values,
                     W_phi, b_phi, W_proj, b_proj, out, write_preds, sm);
        gbar(++epoch);
    }
}

// ---------------- host launcher ----------------
extern "C" void kernel_launch(void* const* d_in, const int* in_sizes, int n_in,
                              void* d_out, int out_size) {
    const float* keys   = (const float*)d_in[0];
    const float* values = (const float*)d_in[1];
    const float* emb    = (const float*)d_in[2];
    const float* W_phi  = (const float*)d_in[3];
    const float* b_phi  = (const float*)d_in[4];
    const float* W_ih   = (const float*)d_in[5];
    const float* b_ih   = (const float*)d_in[6];
    const float* W_hh   = (const float*)d_in[7];
    const float* b_hh   = (const float*)d_in[8];
    const float* W_proj = (const float*)d_in[9];
    const float* b_proj = (const float*)d_in[10];
    const float* h0     = (const float*)d_in[11];
    const float* c0     = (const float*)d_in[12];
    float* out = (float*)d_out;

    int write_preds = (out_size >= STEPS * BB * NV + STEPS * BB) ? 1 : 0;

    init_kernel<<<NV + 1, 256>>>(emb, W_ih, b_ih, b_hh, h0, c0);
    decoder_persistent<<<NBLK, NTHR>>>(keys, values, W_phi, b_phi, W_ih, W_hh,
                                       W_proj, b_proj, out, write_preds);
}

// round 5
// speedup vs baseline: 1.3303x; 1.3303x over previous
#include <cuda_runtime.h>
#include <cuda_fp16.h>
#include <math.h>

#define BB    128
#define TT    2048
#define KD    128
#define VD    128
#define HD    300
#define ED    400
#define NV    33
#define G4    1200
#define SOS   5
#define STEPS 500
#define NBLK  128
#define NTHR  512
#define TRB   256   // transpose blocks in init

// ---------------- persistent device state ----------------
__device__ float g_hA[BB * HD];
__device__ float g_hB[BB * HD];
__device__ float g_c[BB * HD];
__device__ float g_ctx[BB * VD];
__device__ float g_ge[NV * G4];   // emb @ W_ih[:, :400]^T + b_ih + b_hh
__device__ int   g_char[BB];
__device__ unsigned g_count;
__device__ volatile unsigned g_sense;
// fp16 batch-major copies [b][t][k], stored as uint4 (8 halves) for hard
// 16-byte alignment (LDG.128/STG.128 safe).
__device__ uint4 g_keys4[(size_t)BB * TT * (KD / 8)];
__device__ uint4 g_vals4[(size_t)BB * TT * (VD / 8)];

union U4 { uint4 u; __half2 h[4]; };

// ---------------- grid barrier (monotonic epoch) ----------------
__device__ __forceinline__ void gbar(unsigned e) {
    __syncthreads();
    if (threadIdx.x == 0) {
        __threadfence();
        unsigned prev = atomicAdd(&g_count, 1u);
        if (prev == e * NBLK - 1u) {
            g_sense = e;
        } else {
            while (g_sense < e) { }
        }
        __threadfence();
    }
    __syncthreads();
}

// ---------------- init: precompute + transpose + state reset ----------------
__global__ void init_kernel(const float* __restrict__ keys,
                            const float* __restrict__ values,
                            const float* __restrict__ emb,
                            const float* __restrict__ W_ih,
                            const float* __restrict__ b_ih,
                            const float* __restrict__ b_hh,
                            const float* __restrict__ h0,
                            const float* __restrict__ c0) {
    int blk = blockIdx.x, tid = threadIdx.x;
    if (blk < NV) {
        __shared__ float e_s[ED];
        for (int i = tid; i < ED; i += blockDim.x) e_s[i] = emb[blk * ED + i];
        __syncthreads();
        int wid = tid >> 5, lane = tid & 31;
        for (int j = wid; j < G4; j += 8) {
            float acc = 0.f;
            const float* wr = W_ih + (size_t)j * 528;
            for (int k = lane; k < ED; k += 32) acc += e_s[k] * wr[k];
            #pragma unroll
            for (int o = 16; o; o >>= 1) acc += __shfl_xor_sync(0xffffffffu, acc, o);
            if (lane == 0) g_ge[blk * G4 + j] = acc + b_ih[j] + b_hh[j];
        }
    } else if (blk == NV) {
        for (int i = tid; i < BB * HD; i += blockDim.x) {
            g_hA[i] = h0[i % HD];
            g_c[i]  = c0[i % HD];
        }
        for (int i = tid; i < BB; i += blockDim.x) g_char[i] = SOS;
        if (tid == 0) { g_count = 0u; g_sense = 0u; }
    } else {
        // transpose+convert: [t][b][k] f32 -> [b][t][k] f16, 8 elems per chunk
        const int CH = TT * BB * KD / 8;            // chunks per tensor
        int xb = blk - NV - 1;
        for (int c = xb * blockDim.x + tid; c < 2 * CH; c += TRB * blockDim.x) {
            int isV = c >= CH;
            int cc = isV ? c - CH : c;
            const float4* src = (const float4*)(isV ? values : keys) + (size_t)cc * 2;
            float4 a = src[0], b4 = src[1];
            U4 o;
            o.h[0] = __floats2half2_rn(a.x, a.y);
            o.h[1] = __floats2half2_rn(a.z, a.w);
            o.h[2] = __floats2half2_rn(b4.x, b4.y);
            o.h[3] = __floats2half2_rn(b4.z, b4.w);
            int kc = cc & 15;                // k-chunk (8 halves)
            int b  = (cc >> 4) & 127;
            int t  = cc >> 11;
            uint4* dst = isV ? g_vals4 : g_keys4;
            dst[((size_t)b * TT + t) * 16 + kc] = o.u;
        }
    }
}

// ---------------- attend phase (+ fused logits/argmax prologue) ----------------
__device__ void attend_phase(int b, const float* __restrict__ hbuf, int s,
                             const float* __restrict__ W_phi,
                             const float* __restrict__ b_phi,
                             const float* __restrict__ W_proj,
                             const float* __restrict__ b_proj,
                             float* __restrict__ out, int write_preds,
                             float* sm) {
    int tid = threadIdx.x, wid = tid >> 5, lane = tid & 31;
    float* w_s   = sm;          // 2048
    float* cpart = sm + 2048;   // 4096
    float* h_s   = sm + 6144;   // 304
    float* q_s   = sm + 6448;   // 128 (16B aligned)
    float* ctx_s = sm + 6576;   // 128
    float* lg_s  = sm + 6704;   // 36
    float* red   = sm + 6740;   // 16
    float* bc    = sm + 6756;   // 2

    for (int i = tid; i < HD; i += NTHR) h_s[i] = __ldcg(&hbuf[b * HD + i]);
    for (int i = tid; i < VD; i += NTHR) ctx_s[i] = __ldcg(&g_ctx[b * VD + i]);
    __syncthreads();

    if (s >= 0) {
        for (int v = wid; v < NV; v += 16) {
            float acc = 0.f;
            const float* wr = W_proj + (size_t)v * 428;
            for (int k = lane; k < 428; k += 32) {
                float x = (k < HD) ? h_s[k] : ctx_s[k - HD];
                acc += x * wr[k];
            }
            #pragma unroll
            for (int o = 16; o; o >>= 1) acc += __shfl_xor_sync(0xffffffffu, acc, o);
            if (lane == 0) lg_s[v] = acc + b_proj[v];
        }
        __syncthreads();
        if (tid < NV) out[(size_t)s * (BB * NV) + b * NV + tid] = lg_s[tid];
        if (tid == 0) {
            int am = 0; float mv = lg_s[0];
            for (int v = 1; v < NV; ++v) if (lg_s[v] > mv) { mv = lg_s[v]; am = v; }
            __stcg(&g_char[b], am);
            if (write_preds)
                out[(size_t)STEPS * BB * NV + (size_t)s * BB + b] = (float)am;
        }
    }

    // query = h @ W_phi^T + b_phi
    for (int q = wid; q < KD; q += 16) {
        float acc = 0.f;
        const float* wr = W_phi + (size_t)q * HD;
        for (int k = lane; k < HD; k += 32) acc += h_s[k] * wr[k];
        #pragma unroll
        for (int o = 16; o; o >>= 1) acc += __shfl_xor_sync(0xffffffffu, acc, o);
        if (lane == 0) q_s[q] = acc + b_phi[q];
    }
    __syncthreads();

    // ---- energies: fp16 keys, batch-major; lane = (t_sub, k_chunk) ----
    {
        int kc = lane & 15;         // 8 k-values per lane
        int ts = lane >> 4;         // 2 t per load batch
        float4 qa = ((const float4*)q_s)[kc * 2];
        float4 qb = ((const float4*)q_s)[kc * 2 + 1];
        const uint4* kb = g_keys4 + (size_t)b * TT * 16;
        for (int t0 = wid * 16; t0 < TT; t0 += 256) {
            U4 kv[8];
            #pragma unroll
            for (int i = 0; i < 8; i++)
                kv[i].u = __ldg(&kb[(size_t)(t0 + 2 * i + ts) * 16 + kc]);
            #pragma unroll
            for (int i = 0; i < 8; i++) {
                float2 f0 = __half22float2(kv[i].h[0]);
                float2 f1 = __half22float2(kv[i].h[1]);
                float2 f2 = __half22float2(kv[i].h[2]);
                float2 f3 = __half22float2(kv[i].h[3]);
                float e = f0.x * qa.x + f0.y * qa.y + f1.x * qa.z + f1.y * qa.w
                        + f2.x * qb.x + f2.y * qb.y + f3.x * qb.z + f3.y * qb.w;
                #pragma unroll
                for (int o = 8; o; o >>= 1) e += __shfl_xor_sync(0xffffffffu, e, o);
                if (kc == 0) w_s[t0 + 2 * i + ts] = e;
            }
        }
    }
    __syncthreads();

    // softmax max
    float m = -1e30f;
    for (int i = tid; i < TT; i += NTHR) m = fmaxf(m, w_s[i]);
    #pragma unroll
    for (int o = 16; o; o >>= 1) m = fmaxf(m, __shfl_xor_sync(0xffffffffu, m, o));
    if (lane == 0) red[wid] = m;
    __syncthreads();
    if (wid == 0) {
        float v = (lane < 16) ? red[lane] : -1e30f;
        #pragma unroll
        for (int o = 8; o; o >>= 1) v = fmaxf(v, __shfl_xor_sync(0xffffffffu, v, o));
        if (lane == 0) bc[0] = v;
    }
    __syncthreads();
    m = bc[0];

    // exp + sum
    float lsum = 0.f;
    for (int i = tid; i < TT; i += NTHR) {
        float e = expf(w_s[i] - m);
        w_s[i] = e;
        lsum += e;
    }
    #pragma unroll
    for (int o = 16; o; o >>= 1) lsum += __shfl_xor_sync(0xffffffffu, lsum, o);
    if (lane == 0) red[wid] = lsum;
    __syncthreads();
    if (wid == 0) {
        float v = (lane < 16) ? red[lane] : 0.f;
        #pragma unroll
        for (int o = 8; o; o >>= 1) v += __shfl_xor_sync(0xffffffffu, v, o);
        if (lane == 0) bc[1] = v;
    }
    __syncthreads();
    float inv = 1.f / bc[1];

    // ---- context: fp16 values; 32 t-groups x 16 v-chunks ----
    {
        int kc = tid & 15;          // 8 v-values per thread
        int tg = tid >> 4;          // 32 t-groups
        const uint4* vb = g_vals4 + (size_t)b * TT * 16;
        float a0=0,a1=0,a2=0,a3=0,a4=0,a5=0,a6=0,a7=0;
        for (int t0 = tg; t0 < TT; t0 += 256) {
            U4 vv[8];
            #pragma unroll
            for (int j = 0; j < 8; j++)
                vv[j].u = __ldg(&vb[(size_t)(t0 + j * 32) * 16 + kc]);
            #pragma unroll
            for (int j = 0; j < 8; j++) {
                float w = w_s[t0 + j * 32];
                float2 f0 = __half22float2(vv[j].h[0]);
                float2 f1 = __half22float2(vv[j].h[1]);
                float2 f2 = __half22float2(vv[j].h[2]);
                float2 f3 = __half22float2(vv[j].h[3]);
                a0 += w * f0.x; a1 += w * f0.y; a2 += w * f1.x; a3 += w * f1.y;
                a4 += w * f2.x; a5 += w * f2.y; a6 += w * f3.x; a7 += w * f3.y;
            }
        }
        float4* cp4 = (float4*)cpart;
        cp4[tg * 32 + kc * 2]     = make_float4(a0, a1, a2, a3);
        cp4[tg * 32 + kc * 2 + 1] = make_float4(a4, a5, a6, a7);
    }
    __syncthreads();
    if (tid < 128) {
        float acc = 0.f;
        #pragma unroll
        for (int g = 0; g < 32; g++) acc += cpart[g * 128 + tid];
        __stcg(&g_ctx[b * VD + tid], acc * inv);
    }
    __syncthreads();
}

// ---------------- LSTM phase ----------------
__device__ void lstm_phase(int parity,
                           const float* __restrict__ W_ih,
                           const float* __restrict__ W_hh,
                           float* sm) {
    int cta = blockIdx.x;
    if (cta >= 120) return;
    int tid = threadIdx.x;
    int bt = cta / 15;
    int nt = cta % 15;
    const float* h_in  = parity ? g_hB : g_hA;
    float*       h_out = parity ? g_hA : g_hB;

    float* xx = sm;             // [16][432] = 6912 floats (sm must be >= 6912!)
    for (int idx = tid; idx < 16 * 428; idx += NTHR) {
        int bl = idx / 428, k = idx - bl * 428;
        int bg = bt * 16 + bl;
        float v = (k < 128) ? __ldcg(&g_ctx[bg * 128 + k])
                            : __ldcg(&h_in[bg * 300 + (k - 128)]);
        xx[bl * 432 + k] = v;
    }
    __syncthreads();

    float acc[4][4];
    int ks = 0, rem = 0;
    if (tid < 320) {
        ks = tid / 80; rem = tid % 80;
        int rg = rem / 4, bg = rem % 4;
        int gq = (rg * 4) / 20, rl = (rg * 4) % 20;
        int row0 = gq * 300 + nt * 20 + rl;
        #pragma unroll
        for (int r = 0; r < 4; r++)
            #pragma unroll
            for (int bi = 0; bi < 4; bi++) acc[r][bi] = 0.f;

        int k4s = ks * 27, k4e = (ks == 3) ? 107 : (k4s + 27);
        const float4* xb[4];
        #pragma unroll
        for (int bi = 0; bi < 4; bi++)
            xb[bi] = (const float4*)(xx + (size_t)(bg * 4 + bi) * 432);

        int e1 = k4e < 32 ? k4e : 32;
        for (int k4 = k4s; k4 < e1; k4++) {
            float4 w[4];
            #pragma unroll
            for (int r = 0; r < 4; r++)
                w[r] = __ldg((const float4*)(W_ih + (size_t)(row0 + r) * 528 + 400) + k4);
            #pragma unroll
            for (int bi = 0; bi < 4; bi++) {
                float4 x = xb[bi][k4];
                #pragma unroll
                for (int r = 0; r < 4; r++)
                    acc[r][bi] += w[r].x * x.x + w[r].y * x.y + w[r].z * x.z + w[r].w * x.w;
            }
        }
        int s2 = k4s > 32 ? k4s : 32;
        for (int k4 = s2; k4 < k4e; k4++) {
            float4 w[4];
            #pragma unroll
            for (int r = 0; r < 4; r++)
                w[r] = __ldg((const float4*)(W_hh + (size_t)(row0 + r) * 300) + (k4 - 32));
            #pragma unroll
            for (int bi = 0; bi < 4; bi++) {
                float4 x = xb[bi][k4];
                #pragma unroll
                for (int r = 0; r < 4; r++)
                    acc[r][bi] += w[r].x * x.x + w[r].y * x.y + w[r].z * x.z + w[r].w * x.w;
            }
        }
    }
    __syncthreads();

    float* part = sm;           // 5120 floats
    float* gs   = sm + 5120;    // 1280 floats
    if (tid < 320) {
        #pragma unroll
        for (int r = 0; r < 4; r++)
            #pragma unroll
            for (int bi = 0; bi < 4; bi++)
                part[(rem * 16 + r * 4 + bi) * 4 + ks] = acc[r][bi];
    }
    __syncthreads();

    for (int o = tid; o < 1280; o += NTHR) {
        float sum = part[o * 4] + part[o * 4 + 1] + part[o * 4 + 2] + part[o * 4 + 3];
        int rm = o >> 4, ri = (o >> 2) & 3, bi = o & 3;
        int rg = rm >> 2, bg = rm & 3;
        int r = rg * 4 + ri;
        int bl = bg * 4 + bi;
        int gq = r / 20, nl = r % 20;
        int row = gq * 300 + nt * 20 + nl;
        int ch = __ldcg(&g_char[bt * 16 + bl]);
        sum += g_ge[ch * G4 + row];
        gs[(bl * 20 + nl) * 4 + gq] = sum;
    }
    __syncthreads();

    if (tid < 320) {
        int bl = tid / 20, nl = tid % 20;
        float4 gv = *(const float4*)(gs + (bl * 20 + nl) * 4);
        int bg = bt * 16 + bl, ng = nt * 20 + nl;
        float c_old = g_c[bg * 300 + ng];
        float ig = 1.f / (1.f + expf(-gv.x));
        float fg = 1.f / (1.f + expf(-gv.y));
        float gg = tanhf(gv.z);
        float og = 1.f / (1.f + expf(-gv.w));
        float cn = fg * c_old + ig * gg;
        float hn = og * tanhf(cn);
        g_c[bg * 300 + ng] = cn;
        __stcg(&h_out[bg * 300 + ng], hn);
    }
    __syncthreads();
}

// ---------------- persistent kernel ----------------
__global__ void __launch_bounds__(NTHR, 1)
decoder_persistent(const float* __restrict__ W_phi,
                   const float* __restrict__ b_phi,
                   const float* __restrict__ W_ih,
                   const float* __restrict__ W_hh,
                   const float* __restrict__ W_proj,
                   const float* __restrict__ b_proj,
                   float* __restrict__ out, int write_preds) {
    // 7168 floats: lstm xx tile needs 16*432 = 6912 (R3/R4 had 6784 -> smem OOB!)
    __shared__ __align__(16) float sm[7168];
    int cta = blockIdx.x;
    unsigned epoch = 0;

    attend_phase(cta, g_hA, -1, W_phi, b_phi, W_proj, b_proj, out, 0, sm);
    gbar(++epoch);

    for (int s = 0; s < STEPS; ++s) {
        lstm_phase(s & 1, W_ih, W_hh, sm);
        gbar(++epoch);
        attend_phase(cta, (s & 1) ? g_hA : g_hB, s, W_phi, b_phi,
                     W_proj, b_proj, out, write_preds, sm);
        gbar(++epoch);
    }
}

// ---------------- host launcher ----------------
extern "C" void kernel_launch(void* const* d_in, const int* in_sizes, int n_in,
                              void* d_out, int out_size) {
    const float* keys   = (const float*)d_in[0];
    const float* values = (const float*)d_in[1];
    const float* emb    = (const float*)d_in[2];
    const float* W_phi  = (const float*)d_in[3];
    const float* b_phi  = (const float*)d_in[4];
    const float* W_ih   = (const float*)d_in[5];
    const float* b_ih   = (const float*)d_in[6];
    const float* W_hh   = (const float*)d_in[7];
    const float* b_hh   = (const float*)d_in[8];
    const float* W_proj = (const float*)d_in[9];
    const float* b_proj = (const float*)d_in[10];
    const float* h0     = (const float*)d_in[11];
    const float* c0     = (const float*)d_in[12];
    float* out = (float*)d_out;

    int write_preds = (out_size >= STEPS * BB * NV + STEPS * BB) ? 1 : 0;

    init_kernel<<<NV + 1 + TRB, 256>>>(keys, values, emb, W_ih, b_ih, b_hh, h0, c0);
    decoder_persistent<<<NBLK, NTHR>>>(W_phi, b_phi, W_ih, W_hh,
                                       W_proj, b_proj, out, write_preds);
}

// round 6
// speedup vs baseline: 1.3756x; 1.0341x over previous
#include <cuda_runtime.h>
#include <cuda_fp16.h>
#include <math.h>

#define BB    128
#define TT    2048
#define KD    128
#define VD    128
#define HD    300
#define ED    400
#define NV    33
#define G4    1200
#define SOS   5
#define STEPS 500
#define NBLK  128
#define NTHR  512
#define TRB   256   // transpose blocks in init

// ---------------- persistent device state ----------------
__device__ float g_hA[BB * HD];
__device__ float g_hB[BB * HD];
__device__ float g_c[BB * HD];
__device__ float g_ctx[BB * VD];
__device__ float g_ge[NV * G4];   // emb @ W_ih[:, :400]^T + b_ih + b_hh
__device__ int   g_char[BB];
__device__ unsigned g_count;
__device__ volatile unsigned g_sense;
// fp16 batch-major copies [b][t][k], stored as uint4 (8 halves) for hard
// 16-byte alignment (LDG.128/STG.128 safe).
__device__ uint4 g_keys4[(size_t)BB * TT * (KD / 8)];
__device__ uint4 g_vals4[(size_t)BB * TT * (VD / 8)];

union U4 { uint4 u; __half2 h[4]; };

__device__ __forceinline__ float sigf(float x) { return 1.f / (1.f + __expf(-x)); }
__device__ __forceinline__ float tanf_(float x) { return 2.f / (1.f + __expf(-2.f * x)) - 1.f; }

// ---------------- grid barrier (monotonic epoch) ----------------
__device__ __forceinline__ void gbar(unsigned e) {
    __syncthreads();
    if (threadIdx.x == 0) {
        __threadfence();
        unsigned prev = atomicAdd(&g_count, 1u);
        if (prev == e * NBLK - 1u) {
            g_sense = e;
        } else {
            while (g_sense < e) { }
        }
        __threadfence();
    }
    __syncthreads();
}

// ---------------- init: precompute + transpose + state reset ----------------
__global__ void init_kernel(const float* __restrict__ keys,
                            const float* __restrict__ values,
                            const float* __restrict__ emb,
                            const float* __restrict__ W_ih,
                            const float* __restrict__ b_ih,
                            const float* __restrict__ b_hh,
                            const float* __restrict__ h0,
                            const float* __restrict__ c0) {
    int blk = blockIdx.x, tid = threadIdx.x;
    if (blk < NV) {
        __shared__ float e_s[ED];
        for (int i = tid; i < ED; i += blockDim.x) e_s[i] = emb[blk * ED + i];
        __syncthreads();
        int wid = tid >> 5, lane = tid & 31;
        for (int j = wid; j < G4; j += 8) {
            float acc = 0.f;
            const float* wr = W_ih + (size_t)j * 528;
            for (int k = lane; k < ED; k += 32) acc += e_s[k] * wr[k];
            #pragma unroll
            for (int o = 16; o; o >>= 1) acc += __shfl_xor_sync(0xffffffffu, acc, o);
            if (lane == 0) g_ge[blk * G4 + j] = acc + b_ih[j] + b_hh[j];
        }
    } else if (blk == NV) {
        for (int i = tid; i < BB * HD; i += blockDim.x) {
            g_hA[i] = h0[i % HD];
            g_c[i]  = c0[i % HD];
        }
        for (int i = tid; i < BB; i += blockDim.x) g_char[i] = SOS;
        if (tid == 0) { g_count = 0u; g_sense = 0u; }
    } else {
        // transpose+convert: [t][b][k] f32 -> [b][t][k] f16, 8 elems per chunk
        const int CH = TT * BB * KD / 8;            // chunks per tensor
        int xb = blk - NV - 1;
        for (int c = xb * blockDim.x + tid; c < 2 * CH; c += TRB * blockDim.x) {
            int isV = c >= CH;
            int cc = isV ? c - CH : c;
            const float4* src = (const float4*)(isV ? values : keys) + (size_t)cc * 2;
            float4 a = src[0], b4 = src[1];
            U4 o;
            o.h[0] = __floats2half2_rn(a.x, a.y);
            o.h[1] = __floats2half2_rn(a.z, a.w);
            o.h[2] = __floats2half2_rn(b4.x, b4.y);
            o.h[3] = __floats2half2_rn(b4.z, b4.w);
            int kc = cc & 15;                // k-chunk (8 halves)
            int b  = (cc >> 4) & 127;
            int t  = cc >> 11;
            uint4* dst = isV ? g_vals4 : g_keys4;
            dst[((size_t)b * TT + t) * 16 + kc] = o.u;
        }
    }
}

// ---------------- attend phase: fused online-softmax sweep ----------------
__device__ void attend_phase(int b, const float* __restrict__ hbuf, int s,
                             const float* __restrict__ W_phi,
                             const float* __restrict__ b_phi,
                             const float* __restrict__ W_proj,
                             const float* __restrict__ b_proj,
                             float* __restrict__ out, int write_preds,
                             float* sm) {
    int tid = threadIdx.x, wid = tid >> 5, lane = tid & 31;
    float* cpart = sm;          // 2048 (16 warps * 128)
    float* h_s   = sm + 2048;   // 304
    float* q_s   = sm + 2352;   // 128 (16B aligned)
    float* ctx_s = sm + 2480;   // 128
    float* lg_s  = sm + 2608;   // 36
    float* redm  = sm + 2644;   // 16
    float* reds  = sm + 2660;   // 16

    for (int i = tid; i < HD; i += NTHR) h_s[i] = __ldcg(&hbuf[b * HD + i]);
    for (int i = tid; i < VD; i += NTHR) ctx_s[i] = __ldcg(&g_ctx[b * VD + i]);
    __syncthreads();

    if (s >= 0) {
        // logits: h_new + previous context
        for (int v = wid; v < NV; v += 16) {
            float acc = 0.f;
            const float* wr = W_proj + (size_t)v * 428;
            for (int k = lane; k < 428; k += 32) {
                float x = (k < HD) ? h_s[k] : ctx_s[k - HD];
                acc += x * wr[k];
            }
            #pragma unroll
            for (int o = 16; o; o >>= 1) acc += __shfl_xor_sync(0xffffffffu, acc, o);
            if (lane == 0) lg_s[v] = acc + b_proj[v];
        }
        __syncthreads();
        if (tid < NV) out[(size_t)s * (BB * NV) + b * NV + tid] = lg_s[tid];
        if (tid == 0) {
            int am = 0; float mv = lg_s[0];
            for (int v = 1; v < NV; ++v) if (lg_s[v] > mv) { mv = lg_s[v]; am = v; }
            __stcg(&g_char[b], am);
            if (write_preds)
                out[(size_t)STEPS * BB * NV + (size_t)s * BB + b] = (float)am;
        }
    }

    // query = h @ W_phi^T + b_phi
    for (int q = wid; q < KD; q += 16) {
        float acc = 0.f;
        const float* wr = W_phi + (size_t)q * HD;
        for (int k = lane; k < HD; k += 32) acc += h_s[k] * wr[k];
        #pragma unroll
        for (int o = 16; o; o >>= 1) acc += __shfl_xor_sync(0xffffffffu, acc, o);
        if (lane == 0) q_s[q] = acc + b_phi[q];
    }
    __syncthreads();

    // ---- fused sweep: keys+values streamed together, online softmax ----
    {
        int kc = lane & 15;         // k/v chunk of 8 halves
        int ts = lane >> 4;         // t parity within iteration
        float4 qa = ((const float4*)q_s)[kc * 2];
        float4 qb = ((const float4*)q_s)[kc * 2 + 1];
        const uint4* kb = g_keys4 + (size_t)b * TT * 16;
        const uint4* vb = g_vals4 + (size_t)b * TT * 16;

        float m = -1e30f, ssum = 0.f;
        float va[8];
        #pragma unroll
        for (int j = 0; j < 8; j++) va[j] = 0.f;

        for (int t0 = wid * 16; t0 < TT; t0 += 256) {
            U4 kv[8], vv[8];
            #pragma unroll
            for (int i = 0; i < 8; i++) {
                size_t off = (size_t)(t0 + 2 * i + ts) * 16 + kc;
                kv[i].u = __ldg(&kb[off]);
                vv[i].u = __ldg(&vb[off]);
            }
            float e[8];
            #pragma unroll
            for (int i = 0; i < 8; i++) {
                float2 f0 = __half22float2(kv[i].h[0]);
                float2 f1 = __half22float2(kv[i].h[1]);
                float2 f2 = __half22float2(kv[i].h[2]);
                float2 f3 = __half22float2(kv[i].h[3]);
                e[i] = f0.x * qa.x + f0.y * qa.y + f1.x * qa.z + f1.y * qa.w
                     + f2.x * qb.x + f2.y * qb.y + f3.x * qb.z + f3.y * qb.w;
            }
            #pragma unroll
            for (int o = 8; o; o >>= 1) {
                #pragma unroll
                for (int i = 0; i < 8; i++)
                    e[i] += __shfl_xor_sync(0xffffffffu, e[i], o);
            }
            // block max across both t-parity halves (warp-uniform)
            float bm = e[0];
            #pragma unroll
            for (int i = 1; i < 8; i++) bm = fmaxf(bm, e[i]);
            bm = fmaxf(bm, __shfl_xor_sync(0xffffffffu, bm, 16));
            float mn = fmaxf(m, bm);
            float sc = __expf(m - mn);
            m = mn;
            float w[8], ls = 0.f;
            #pragma unroll
            for (int i = 0; i < 8; i++) { w[i] = __expf(e[i] - mn); ls += w[i]; }
            ssum = ssum * sc + ls;
            #pragma unroll
            for (int j = 0; j < 8; j++) va[j] *= sc;
            #pragma unroll
            for (int i = 0; i < 8; i++) {
                float2 f0 = __half22float2(vv[i].h[0]);
                float2 f1 = __half22float2(vv[i].h[1]);
                float2 f2 = __half22float2(vv[i].h[2]);
                float2 f3 = __half22float2(vv[i].h[3]);
                va[0] += w[i] * f0.x; va[1] += w[i] * f0.y;
                va[2] += w[i] * f1.x; va[3] += w[i] * f1.y;
                va[4] += w[i] * f2.x; va[5] += w[i] * f2.y;
                va[6] += w[i] * f3.x; va[7] += w[i] * f3.y;
            }
        }
        // merge t-parity halves (same m across warp)
        ssum += __shfl_xor_sync(0xffffffffu, ssum, 16);
        #pragma unroll
        for (int j = 0; j < 8; j++)
            va[j] += __shfl_xor_sync(0xffffffffu, va[j], 16);
        if (ts == 0) {
            #pragma unroll
            for (int j = 0; j < 8; j++) cpart[wid * 128 + kc * 8 + j] = va[j];
        }
        if (lane == 0) { redm[wid] = m; reds[wid] = ssum; }
    }
    __syncthreads();

    // final cross-warp combine
    if (tid < 128) {
        float M = redm[0];
        #pragma unroll
        for (int w = 1; w < 16; w++) M = fmaxf(M, redm[w]);
        float S = 0.f, cx = 0.f;
        #pragma unroll
        for (int w = 0; w < 16; w++) {
            float f = __expf(redm[w] - M);
            S += reds[w] * f;
            cx += cpart[w * 128 + tid] * f;
        }
        __stcg(&g_ctx[b * VD + tid], cx / S);
    }
    __syncthreads();
}

// ---------------- LSTM phase ----------------
__device__ void lstm_phase(int parity,
                           const float* __restrict__ W_ih,
                           const float* __restrict__ W_hh,
                           float* sm) {
    int cta = blockIdx.x;
    if (cta >= 120) return;
    int tid = threadIdx.x;
    int bt = cta / 15;
    int nt = cta % 15;
    const float* h_in  = parity ? g_hB : g_hA;
    float*       h_out = parity ? g_hA : g_hB;

    float* xx = sm;             // [16][432] = 6912 floats
    for (int idx = tid; idx < 16 * 428; idx += NTHR) {
        int bl = idx / 428, k = idx - bl * 428;
        int bg = bt * 16 + bl;
        float v = (k < 128) ? __ldcg(&g_ctx[bg * 128 + k])
                            : __ldcg(&h_in[bg * 300 + (k - 128)]);
        xx[bl * 432 + k] = v;
    }
    __syncthreads();

    float acc[4][4];
    int ks = 0, rem = 0;
    if (tid < 320) {
        ks = tid / 80; rem = tid % 80;
        int rg = rem / 4, bg = rem % 4;
        int gq = (rg * 4) / 20, rl = (rg * 4) % 20;
        int row0 = gq * 300 + nt * 20 + rl;
        #pragma unroll
        for (int r = 0; r < 4; r++)
            #pragma unroll
            for (int bi = 0; bi < 4; bi++) acc[r][bi] = 0.f;

        int k4s = ks * 27, k4e = (ks == 3) ? 107 : (k4s + 27);
        const float4* xb[4];
        #pragma unroll
        for (int bi = 0; bi < 4; bi++)
            xb[bi] = (const float4*)(xx + (size_t)(bg * 4 + bi) * 432);

        int e1 = k4e < 32 ? k4e : 32;
        for (int k4 = k4s; k4 < e1; k4++) {
            float4 w[4];
            #pragma unroll
            for (int r = 0; r < 4; r++)
                w[r] = __ldg((const float4*)(W_ih + (size_t)(row0 + r) * 528 + 400) + k4);
            #pragma unroll
            for (int bi = 0; bi < 4; bi++) {
                float4 x = xb[bi][k4];
                #pragma unroll
                for (int r = 0; r < 4; r++)
                    acc[r][bi] += w[r].x * x.x + w[r].y * x.y + w[r].z * x.z + w[r].w * x.w;
            }
        }
        int s2 = k4s > 32 ? k4s : 32;
        for (int k4 = s2; k4 < k4e; k4++) {
            float4 w[4];
            #pragma unroll
            for (int r = 0; r < 4; r++)
                w[r] = __ldg((const float4*)(W_hh + (size_t)(row0 + r) * 300) + (k4 - 32));
            #pragma unroll
            for (int bi = 0; bi < 4; bi++) {
                float4 x = xb[bi][k4];
                #pragma unroll
                for (int r = 0; r < 4; r++)
                    acc[r][bi] += w[r].x * x.x + w[r].y * x.y + w[r].z * x.z + w[r].w * x.w;
            }
        }
    }
    __syncthreads();

    float* part = sm;           // 5120 floats
    float* gs   = sm + 5120;    // 1280 floats
    if (tid < 320) {
        #pragma unroll
        for (int r = 0; r < 4; r++)
            #pragma unroll
            for (int bi = 0; bi < 4; bi++)
                part[(rem * 16 + r * 4 + bi) * 4 + ks] = acc[r][bi];
    }
    __syncthreads();

    for (int o = tid; o < 1280; o += NTHR) {
        float sum = part[o * 4] + part[o * 4 + 1] + part[o * 4 + 2] + part[o * 4 + 3];
        int rm = o >> 4, ri = (o >> 2) & 3, bi = o & 3;
        int rg = rm >> 2, bg = rm & 3;
        int r = rg * 4 + ri;
        int bl = bg * 4 + bi;
        int gq = r / 20, nl = r % 20;
        int row = gq * 300 + nt * 20 + nl;
        int ch = __ldcg(&g_char[bt * 16 + bl]);
        sum += g_ge[ch * G4 + row];
        gs[(bl * 20 + nl) * 4 + gq] = sum;
    }
    __syncthreads();

    if (tid < 320) {
        int bl = tid / 20, nl = tid % 20;
        float4 gv = *(const float4*)(gs + (bl * 20 + nl) * 4);
        int bg = bt * 16 + bl, ng = nt * 20 + nl;
        float c_old = g_c[bg * 300 + ng];
        float ig = sigf(gv.x);
        float fg = sigf(gv.y);
        float gg = tanf_(gv.z);
        float og = sigf(gv.w);
        float cn = fg * c_old + ig * gg;
        float hn = og * tanf_(cn);
        g_c[bg * 300 + ng] = cn;
        __stcg(&h_out[bg * 300 + ng], hn);
    }
    __syncthreads();
}

// ---------------- persistent kernel ----------------
__global__ void __launch_bounds__(NTHR, 1)
decoder_persistent(const float* __restrict__ W_phi,
                   const float* __restrict__ b_phi,
                   const float* __restrict__ W_ih,
                   const float* __restrict__ W_hh,
                   const float* __restrict__ W_proj,
                   const float* __restrict__ b_proj,
                   float* __restrict__ out, int write_preds) {
    // 7168 floats: lstm xx tile needs 16*432 = 6912
    __shared__ __align__(16) float sm[7168];
    int cta = blockIdx.x;
    unsigned epoch = 0;

    attend_phase(cta, g_hA, -1, W_phi, b_phi, W_proj, b_proj, out, 0, sm);
    gbar(++epoch);

    for (int s = 0; s < STEPS; ++s) {
        lstm_phase(s & 1, W_ih, W_hh, sm);
        gbar(++epoch);
        attend_phase(cta, (s & 1) ? g_hA : g_hB, s, W_phi, b_phi,
                     W_proj, b_proj, out, write_preds, sm);
        gbar(++epoch);
    }
}

// ---------------- host launcher ----------------
extern "C" void kernel_launch(void* const* d_in, const int* in_sizes, int n_in,
                              void* d_out, int out_size) {
    const float* keys   = (const float*)d_in[0];
    const float* values = (const float*)d_in[1];
    const float* emb    = (const float*)d_in[2];
    const float* W_phi  = (const float*)d_in[3];
    const float* b_phi  = (const float*)d_in[4];
    const float* W_ih   = (const float*)d_in[5];
    const float* b_ih   = (const float*)d_in[6];
    const float* W_hh   = (const float*)d_in[7];
    const float* b_hh   = (const float*)d_in[8];
    const float* W_proj = (const float*)d_in[9];
    const float* b_proj = (const float*)d_in[10];
    const float* h0     = (const float*)d_in[11];
    const float* c0     = (const float*)d_in[12];
    float* out = (float*)d_out;

    int write_preds = (out_size >= STEPS * BB * NV + STEPS * BB) ? 1 : 0;

    init_kernel<<<NV + 1 + TRB, 256>>>(keys, values, emb, W_ih, b_ih, b_hh, h0, c0);
    decoder_persistent<<<NBLK, NTHR>>>(W_phi, b_phi, W_ih, W_hh,
                                       W_proj, b_proj, out, write_preds);
}